// round 4
// baseline (speedup 1.0000x reference)
#include <cuda_runtime.h>
#include <cuda_bf16.h>
#include <cstdint>

// Problem constants
#define N_EDGES   32768
#define N_NODES   2048
#define D_IN      128
#define D_FEAT    32
#define D_CAT     160   // D_MEM_A + D_FEAT
#define D_OUT     128

#define NODE_CAP  512   // max edges per node (mean 164, std ~13)
#define EDGE_CAP  64    // max nodes per edge (mean 10.2)

// ---------------- scratch (static device globals; no allocation) -------------
__device__ float g_h[N_EDGES * 128];          // hidden activations (reused)
__device__ float g_s[N_EDGES * 128];          // s = memory MLP output
__device__ float g_nodesum[N_NODES * 128];    // mask @ s
__device__ float g_aggcat[N_EDGES * D_CAT];   // [agg | feature]
__device__ int   g_node_cnt[N_NODES];
__device__ int   g_node_edges[N_NODES * NODE_CAP];
__device__ int   g_edge_cnt[N_EDGES];
__device__ int   g_edge_nodes[N_EDGES * EDGE_CAP];

// ---------------- helpers ----------------------------------------------------
__device__ __forceinline__ float log_sigmoid(float x) {
    // ls(x) = min(x,0) - log1p(exp(-|x|)) : numerically stable
    return fminf(x, 0.0f) - log1pf(__expf(-fabsf(x)));
}

// ---------------- kernel: zero edge counters ---------------------------------
__global__ void zero_edge_cnt_kernel() {
    int i = blockIdx.x * blockDim.x + threadIdx.x;
    if (i < N_EDGES) g_edge_cnt[i] = 0;
}

// ---------------- kernel: fused GEMM + bias + log_sigmoid --------------------
// C[M,128] = log_sigmoid( A[M,K] @ W[128,K]^T + b )
// Block: 64 rows x 128 cols of C, 256 threads, each thread 4x8 microtile.
template <int K, bool HAS_BIAS>
__global__ void __launch_bounds__(256)
gemm_ls_kernel(const float* __restrict__ A, const float* __restrict__ W,
               const float* __restrict__ b, float* __restrict__ C) {
    extern __shared__ float sm[];
    float* At = sm;               // [K][65]  (A transposed, padded)
    float* Ws = sm + K * 65;      // [K][128] (W transposed)

    const int tid  = threadIdx.x;
    const int row0 = blockIdx.x * 64;
    constexpr int KQ = K / 4;

    // --- load A tile (coalesced global, transposed smem store) ---
    const float4* A4 = reinterpret_cast<const float4*>(A + (size_t)row0 * K);
    #pragma unroll 2
    for (int idx = tid; idx < 64 * KQ; idx += 256) {
        int m  = idx / KQ;
        int kq = idx % KQ;
        float4 v = A4[idx];
        At[(kq * 4 + 0) * 65 + m] = v.x;
        At[(kq * 4 + 1) * 65 + m] = v.y;
        At[(kq * 4 + 2) * 65 + m] = v.z;
        At[(kq * 4 + 3) * 65 + m] = v.w;
    }
    // --- load W (bank-conflict-free smem writes: n = lane) ---
    {
        const float4* W4 = reinterpret_cast<const float4*>(W);
        int n = tid & 127;
        for (int kq = (tid >> 7); kq < KQ; kq += 2) {
            float4 v = W4[n * KQ + kq];
            Ws[(kq * 4 + 0) * 128 + n] = v.x;
            Ws[(kq * 4 + 1) * 128 + n] = v.y;
            Ws[(kq * 4 + 2) * 128 + n] = v.z;
            Ws[(kq * 4 + 3) * 128 + n] = v.w;
        }
    }
    __syncthreads();

    const int tr = tid >> 4;   // 0..15 -> rows tr*4 .. tr*4+3
    const int tc = tid & 15;   // 0..15 -> cols tc*8 .. tc*8+7

    float acc[4][8];
    #pragma unroll
    for (int i = 0; i < 4; i++)
        #pragma unroll
        for (int j = 0; j < 8; j++) acc[i][j] = 0.0f;

    #pragma unroll 8
    for (int k = 0; k < K; k++) {
        const float* atk = &At[k * 65 + (tr << 2)];
        float a0 = atk[0], a1 = atk[1], a2 = atk[2], a3 = atk[3];
        const float4* wk = reinterpret_cast<const float4*>(&Ws[k * 128 + (tc << 3)]);
        float4 w0 = wk[0];
        float4 w1 = wk[1];
        float w[8] = {w0.x, w0.y, w0.z, w0.w, w1.x, w1.y, w1.z, w1.w};
        #pragma unroll
        for (int j = 0; j < 8; j++) {
            acc[0][j] = fmaf(a0, w[j], acc[0][j]);
            acc[1][j] = fmaf(a1, w[j], acc[1][j]);
            acc[2][j] = fmaf(a2, w[j], acc[2][j]);
            acc[3][j] = fmaf(a3, w[j], acc[3][j]);
        }
    }

    // --- epilogue: bias + log_sigmoid, vectorized stores ---
    float bb[8];
    if (HAS_BIAS) {
        const float4* b4 = reinterpret_cast<const float4*>(b);
        float4 q0 = b4[tc * 2], q1 = b4[tc * 2 + 1];
        bb[0] = q0.x; bb[1] = q0.y; bb[2] = q0.z; bb[3] = q0.w;
        bb[4] = q1.x; bb[5] = q1.y; bb[6] = q1.z; bb[7] = q1.w;
    } else {
        #pragma unroll
        for (int j = 0; j < 8; j++) bb[j] = 0.0f;
    }
    #pragma unroll
    for (int i = 0; i < 4; i++) {
        int row = row0 + (tr << 2) + i;
        float o[8];
        #pragma unroll
        for (int j = 0; j < 8; j++) o[j] = log_sigmoid(acc[i][j] + bb[j]);
        float4* c4 = reinterpret_cast<float4*>(C + (size_t)row * 128 + (tc << 3));
        c4[0] = make_float4(o[0], o[1], o[2], o[3]);
        c4[1] = make_float4(o[4], o[5], o[6], o[7]);
    }
}

// ---------------- kernel: scan mask rows, build adjacency --------------------
// One block per node. Deterministic node->edge list via smem prefix scan.
// Edge->node lists via global atomics (sorted later in gather kernel).
__global__ void __launch_bounds__(256)
build_lists_kernel(const float* __restrict__ mask) {
    const int n   = blockIdx.x;
    const int tid = threadIdx.x;
    const float4* mrow = reinterpret_cast<const float4*>(mask + (size_t)n * N_EDGES);

    int local[16];
    int c = 0;
    for (int i = tid; i < N_EDGES / 4; i += 256) {
        float4 v = __ldcs(&mrow[i]);
        int e = i * 4;
        if (v.x != 0.0f) { if (c < 16) local[c] = e + 0; c++; }
        if (v.y != 0.0f) { if (c < 16) local[c] = e + 1; c++; }
        if (v.z != 0.0f) { if (c < 16) local[c] = e + 2; c++; }
        if (v.w != 0.0f) { if (c < 16) local[c] = e + 3; c++; }
    }
    c = min(c, 16);

    __shared__ int s_scan[256];
    s_scan[tid] = c;
    __syncthreads();
    #pragma unroll
    for (int off = 1; off < 256; off <<= 1) {
        int v = (tid >= off) ? s_scan[tid - off] : 0;
        __syncthreads();
        s_scan[tid] += v;
        __syncthreads();
    }
    int offset = s_scan[tid] - c;
    int total  = s_scan[255];

    for (int j = 0; j < c; j++) {
        int e   = local[j];
        int pos = offset + j;
        if (pos < NODE_CAP) g_node_edges[n * NODE_CAP + pos] = e;
        int q = atomicAdd(&g_edge_cnt[e], 1);
        if (q < EDGE_CAP) g_edge_nodes[e * EDGE_CAP + q] = n;
    }
    if (tid == 0) g_node_cnt[n] = min(total, NODE_CAP);
}

// ---------------- kernel: nodesum[n] = sum_{e in list(n)} s[e] ---------------
__global__ void __launch_bounds__(128)
node_sum_kernel() {
    const int n = blockIdx.x;
    const int d = threadIdx.x;
    const int cnt = g_node_cnt[n];
    const int* lst = &g_node_edges[n * NODE_CAP];

    float a0 = 0.f, a1 = 0.f, a2 = 0.f, a3 = 0.f;
    int i = 0;
    for (; i + 4 <= cnt; i += 4) {
        int e0 = lst[i], e1 = lst[i + 1], e2 = lst[i + 2], e3 = lst[i + 3];
        a0 += g_s[(size_t)e0 * 128 + d];
        a1 += g_s[(size_t)e1 * 128 + d];
        a2 += g_s[(size_t)e2 * 128 + d];
        a3 += g_s[(size_t)e3 * 128 + d];
    }
    for (; i < cnt; i++) a0 += g_s[(size_t)lst[i] * 128 + d];
    g_nodesum[n * 128 + d] = (a0 + a1) + (a2 + a3);
}

// ---------------- kernel: agg + concat ---------------------------------------
// aggcat[e] = [ sum_{n in list(e)} nodesum[n] - s[e]  |  feature[e] ]
// Edge node-list is rank-sorted for deterministic fp summation order.
__global__ void __launch_bounds__(128)
edge_gather_kernel(const float* __restrict__ feature) {
    const int e   = blockIdx.x;
    const int tid = threadIdx.x;

    __shared__ int sl[EDGE_CAP];
    __shared__ int ss[EDGE_CAP];
    const int cnt = min(g_edge_cnt[e], EDGE_CAP);

    if (tid < cnt) sl[tid] = g_edge_nodes[e * EDGE_CAP + tid];
    __syncthreads();
    if (tid < cnt) {
        int v = sl[tid];
        int r = 0;
        for (int j = 0; j < cnt; j++) r += (sl[j] < v);
        ss[r] = v;   // node ids unique per edge -> ranks distinct
    }
    __syncthreads();

    float acc = -g_s[(size_t)e * 128 + tid];
    for (int i = 0; i < cnt; i++)
        acc += g_nodesum[ss[i] * 128 + tid];
    g_aggcat[(size_t)e * D_CAT + tid] = acc;
    if (tid < D_FEAT)
        g_aggcat[(size_t)e * D_CAT + 128 + tid] = feature[(size_t)e * D_FEAT + tid];
}

// ---------------- launch -----------------------------------------------------
extern "C" void kernel_launch(void* const* d_in, const int* in_sizes, int n_in,
                              void* d_out, int out_size) {
    const float* state    = (const float*)d_in[0];
    const float* feature  = (const float*)d_in[1];
    const float* mask     = (const float*)d_in[2];
    // d_in[3] = mask_transpose (unused: it is exactly mask.T)
    const float* W1_m     = (const float*)d_in[4];
    const float* b1_m     = (const float*)d_in[5];
    const float* W2_m     = (const float*)d_in[6];
    const float* W1_a     = (const float*)d_in[7];
    const float* b1_a     = (const float*)d_in[8];
    const float* W2_a     = (const float*)d_in[9];
    float* out = (float*)d_out;

    // scratch pointers (device symbols resolved at compile time inside kernels)
    const int SMEM128 = 128 * (65 + 128) * 4;   // 98816 B
    const int SMEM160 = 160 * (65 + 128) * 4;   // 123520 B
    cudaFuncSetAttribute(gemm_ls_kernel<128, true>,
                         cudaFuncAttributeMaxDynamicSharedMemorySize, SMEM128);
    cudaFuncSetAttribute(gemm_ls_kernel<128, false>,
                         cudaFuncAttributeMaxDynamicSharedMemorySize, SMEM128);
    cudaFuncSetAttribute(gemm_ls_kernel<160, true>,
                         cudaFuncAttributeMaxDynamicSharedMemorySize, SMEM160);

    float* d_h      = nullptr;
    float* d_s      = nullptr;
    float* d_aggcat = nullptr;
    cudaGetSymbolAddress((void**)&d_h, g_h);
    cudaGetSymbolAddress((void**)&d_s, g_s);
    cudaGetSymbolAddress((void**)&d_aggcat, g_aggcat);

    const int GEMM_BLOCKS = N_EDGES / 64;   // 512

    zero_edge_cnt_kernel<<<N_EDGES / 256, 256>>>();

    // memory MLP: h = ls(state @ W1_m^T + b1_m); s = ls(h @ W2_m^T)
    gemm_ls_kernel<128, true ><<<GEMM_BLOCKS, 256, SMEM128>>>(state, W1_m, b1_m, d_h);
    gemm_ls_kernel<128, false><<<GEMM_BLOCKS, 256, SMEM128>>>(d_h, W2_m, nullptr, d_s);

    // sparse bipartite aggregation (mask read once; transpose never touched)
    build_lists_kernel<<<N_NODES, 256>>>(mask);
    node_sum_kernel<<<N_NODES, 128>>>();
    edge_gather_kernel<<<N_EDGES, 128>>>(feature);

    // aggregation MLP: out = ls(ls(aggcat @ W1_a^T + b1_a) @ W2_a^T)
    gemm_ls_kernel<160, true ><<<GEMM_BLOCKS, 256, SMEM160>>>(d_aggcat, W1_a, b1_a, d_h);
    gemm_ls_kernel<128, false><<<GEMM_BLOCKS, 256, SMEM128>>>(d_h, W2_a, nullptr, out);
}

// round 12
// speedup vs baseline: 1.5013x; 1.5013x over previous
#include <cuda_runtime.h>
#include <cuda_bf16.h>
#include <cstdint>

// Problem constants
#define N_EDGES   32768
#define N_NODES   2048
#define D_FEAT    32
#define D_CAT     160
#define NODE_CAP  512
#define EDGE_CAP  64

// ---------------- scratch (static device globals; no allocation) -------------
__device__ float g_s[N_EDGES * 128];          // s = memory MLP output (fp32)
__device__ float g_nodesum[N_NODES * 128];    // mask @ s
__device__ float g_aggcat[N_EDGES * D_CAT];   // [agg | feature]
__device__ __nv_bfloat16 g_h_hi[N_EDGES * 128];   // split hidden activations
__device__ __nv_bfloat16 g_h_lo[N_EDGES * 128];
__device__ __nv_bfloat16 g_w1m_hi[128 * 128], g_w1m_lo[128 * 128];
__device__ __nv_bfloat16 g_w2m_hi[128 * 128], g_w2m_lo[128 * 128];
__device__ __nv_bfloat16 g_w1a_hi[128 * 160], g_w1a_lo[128 * 160];
__device__ __nv_bfloat16 g_w2a_hi[128 * 128], g_w2a_lo[128 * 128];
__device__ int   g_node_cnt[N_NODES];
__device__ int   g_node_edges[N_NODES * NODE_CAP];
__device__ int   g_edge_cnt[N_EDGES];
__device__ int   g_edge_nodes[N_EDGES * EDGE_CAP];

// ---------------- small helpers ----------------------------------------------
__device__ __forceinline__ float log_sigmoid(float x) {
    return fminf(x, 0.0f) - log1pf(__expf(-fabsf(x)));
}

__device__ __forceinline__ uint32_t smem_u32(const void* p) {
    uint32_t a;
    asm("{ .reg .u64 t; cvta.to.shared.u64 t, %1; cvt.u32.u64 %0, t; }" : "=r"(a) : "l"(p));
    return a;
}

__device__ __forceinline__ uint32_t pack2(__nv_bfloat16 a, __nv_bfloat16 b) {
    __nv_bfloat162 p;
    p.x = a; p.y = b;
    return *reinterpret_cast<uint32_t*>(&p);
}

__device__ __forceinline__ void ldm_x4(uint32_t* r, uint32_t addr) {
    asm volatile("ldmatrix.sync.aligned.m8n8.x4.shared.b16 {%0,%1,%2,%3}, [%4];"
                 : "=r"(r[0]), "=r"(r[1]), "=r"(r[2]), "=r"(r[3]) : "r"(addr));
}

__device__ __forceinline__ void mma16816(float* c, const uint32_t* a, uint32_t b0, uint32_t b1) {
    asm volatile("mma.sync.aligned.m16n8k16.row.col.f32.bf16.bf16.f32 "
                 "{%0,%1,%2,%3}, {%4,%5,%6,%7}, {%8,%9}, {%0,%1,%2,%3};"
                 : "+f"(c[0]), "+f"(c[1]), "+f"(c[2]), "+f"(c[3])
                 : "r"(a[0]), "r"(a[1]), "r"(a[2]), "r"(a[3]), "r"(b0), "r"(b1));
}

// ---------------- kernel: zero edge counters ---------------------------------
__global__ void zero_edge_cnt_kernel() {
    int i = blockIdx.x * blockDim.x + threadIdx.x;
    if (i < N_EDGES) g_edge_cnt[i] = 0;
}

// ---------------- kernel: split weights into bf16 hi/lo ----------------------
__global__ void prep_weights_kernel(const float* __restrict__ w1m,
                                    const float* __restrict__ w2m,
                                    const float* __restrict__ w1a,
                                    const float* __restrict__ w2a) {
    int i = blockIdx.x * blockDim.x + threadIdx.x;
    if (i < 128 * 128) {
        float v = w1m[i];
        __nv_bfloat16 h = __float2bfloat16(v);
        g_w1m_hi[i] = h; g_w1m_lo[i] = __float2bfloat16(v - __bfloat162float(h));
        v = w2m[i]; h = __float2bfloat16(v);
        g_w2m_hi[i] = h; g_w2m_lo[i] = __float2bfloat16(v - __bfloat162float(h));
        v = w2a[i]; h = __float2bfloat16(v);
        g_w2a_hi[i] = h; g_w2a_lo[i] = __float2bfloat16(v - __bfloat162float(h));
    }
    if (i < 128 * 160) {
        float v = w1a[i];
        __nv_bfloat16 h = __float2bfloat16(v);
        g_w1a_hi[i] = h; g_w1a_lo[i] = __float2bfloat16(v - __bfloat162float(h));
    }
}

// ---------------- kernel: HMMA GEMM + bias + log_sigmoid ---------------------
// C[128-tile, 128] = ls( A[tile, K] @ W[128, K]^T + b ), bf16-split 3-product.
// mma.sync.m16n8k16 (HMMA fallback; tcgen05 unavailable: harness PTX targets
// plain sm_103 which rejects tcgen05). 8 warps = 2(M) x 4(N), 64x32 warp tile.
template <int K, bool ASPLIT, bool OUTSPLIT, bool HASBIAS>
__global__ void __launch_bounds__(256, 1)
gemm_mma_kernel(const float* __restrict__ Af,
                const __nv_bfloat16* __restrict__ Ahi,
                const __nv_bfloat16* __restrict__ Alo,
                const __nv_bfloat16* __restrict__ Whi,
                const __nv_bfloat16* __restrict__ Wlo,
                const float* __restrict__ bias,
                float* __restrict__ Cf,
                __nv_bfloat16* __restrict__ Chi,
                __nv_bfloat16* __restrict__ Clo) {
    extern __shared__ char sm[];
    constexpr int LDK = K + 8;            // padded row stride (elements)
    constexpr int T   = 128 * LDK * 2;    // bytes per tile buffer
    float*          s_bias = reinterpret_cast<float*>(sm);
    __nv_bfloat16*  sAhi = reinterpret_cast<__nv_bfloat16*>(sm + 512);
    __nv_bfloat16*  sAlo = reinterpret_cast<__nv_bfloat16*>(sm + 512 + T);
    __nv_bfloat16*  sWhi = reinterpret_cast<__nv_bfloat16*>(sm + 512 + 2 * T);
    __nv_bfloat16*  sWlo = reinterpret_cast<__nv_bfloat16*>(sm + 512 + 3 * T);

    const int tid  = threadIdx.x;
    const int wid  = tid >> 5;
    const int lane = tid & 31;
    const int row0 = blockIdx.x * 128;

    if (HASBIAS && tid < 128) s_bias[tid] = bias[tid];

    // --- fill W tiles (pre-split bf16 hi/lo) ---
    {
        constexpr int NV = 128 * (K / 8);
        const uint4* sh = reinterpret_cast<const uint4*>(Whi);
        const uint4* sl = reinterpret_cast<const uint4*>(Wlo);
        for (int idx = tid; idx < NV; idx += 256) {
            int row = idx / (K / 8);
            int ko  = (idx % (K / 8)) * 8;
            *reinterpret_cast<uint4*>(&sWhi[row * LDK + ko]) = sh[idx];
            *reinterpret_cast<uint4*>(&sWlo[row * LDK + ko]) = sl[idx];
        }
    }
    // --- fill A tiles ---
    if (ASPLIT) {
        constexpr int NV = 128 * (K / 8);
        const uint4* ah = reinterpret_cast<const uint4*>(Ahi + (size_t)row0 * K);
        const uint4* al = reinterpret_cast<const uint4*>(Alo + (size_t)row0 * K);
        for (int idx = tid; idx < NV; idx += 256) {
            int row = idx / (K / 8);
            int ko  = (idx % (K / 8)) * 8;
            *reinterpret_cast<uint4*>(&sAhi[row * LDK + ko]) = ah[idx];
            *reinterpret_cast<uint4*>(&sAlo[row * LDK + ko]) = al[idx];
        }
    } else {
        constexpr int NV = 128 * (K / 4);
        const float4* a4 = reinterpret_cast<const float4*>(Af + (size_t)row0 * K);
        for (int idx = tid; idx < NV; idx += 256) {
            int row = idx / (K / 4);
            int k0  = (idx % (K / 4)) * 4;
            float4 v = a4[idx];
            __nv_bfloat16 h0 = __float2bfloat16(v.x), h1 = __float2bfloat16(v.y);
            __nv_bfloat16 h2 = __float2bfloat16(v.z), h3 = __float2bfloat16(v.w);
            __nv_bfloat16 l0 = __float2bfloat16(v.x - __bfloat162float(h0));
            __nv_bfloat16 l1 = __float2bfloat16(v.y - __bfloat162float(h1));
            __nv_bfloat16 l2 = __float2bfloat16(v.z - __bfloat162float(h2));
            __nv_bfloat16 l3 = __float2bfloat16(v.w - __bfloat162float(h3));
            uint32_t* ph = reinterpret_cast<uint32_t*>(&sAhi[row * LDK + k0]);
            uint32_t* pl = reinterpret_cast<uint32_t*>(&sAlo[row * LDK + k0]);
            ph[0] = pack2(h0, h1); ph[1] = pack2(h2, h3);
            pl[0] = pack2(l0, l1); pl[1] = pack2(l2, l3);
        }
    }
    __syncthreads();

    // --- warp tiling: wm in {0,1} (64 rows), wn in {0..3} (32 cols) ---
    const int wm = wid >> 2;
    const int wn = wid & 3;

    float acc[4][4][4];
    #pragma unroll
    for (int i = 0; i < 4; i++)
        #pragma unroll
        for (int j = 0; j < 4; j++)
            #pragma unroll
            for (int e = 0; e < 4; e++) acc[i][j][e] = 0.0f;

    // ldmatrix base addresses (byte offsets advance with k by +32 per k-step)
    // A tile x4: lanes 0-7 rows r..r+7 @k0 | 8-15 rows +8 @k0 | 16-23 rows r..r+7 @k0+8 | 24-31 rows +8 @k0+8
    const int arow = wm * 64 + (lane & 7) + ((lane >> 3) & 1) * 8;
    const int acol = (lane >> 4) * 8;
    uint32_t aAhi = smem_u32(sAhi) + (uint32_t)(arow * LDK + acol) * 2;
    uint32_t aAlo = smem_u32(sAlo) + (uint32_t)(arow * LDK + acol) * 2;
    // B tile x4 (covers 2 n-frags): lanes 0-7 n..n+7 @k0 | 8-15 n..n+7 @k0+8 | 16-23 n+8 @k0 | 24-31 n+8 @k0+8
    const int brow_base = wn * 32 + (lane & 7) + ((lane >> 4) & 1) * 8;
    const int bcol = ((lane >> 3) & 1) * 8;
    uint32_t aWhi = smem_u32(sWhi) + (uint32_t)(brow_base * LDK + bcol) * 2;
    uint32_t aWlo = smem_u32(sWlo) + (uint32_t)(brow_base * LDK + bcol) * 2;

    constexpr int NK = K / 16;
    #pragma unroll
    for (int ks = 0; ks < NK; ks++) {
        const uint32_t koff = (uint32_t)(ks * 16 * 2);

        uint32_t ah[4][4], al[4][4];
        #pragma unroll
        for (int mf = 0; mf < 4; mf++) {
            ldm_x4(ah[mf], aAhi + koff + (uint32_t)(mf * 16 * LDK * 2));
            ldm_x4(al[mf], aAlo + koff + (uint32_t)(mf * 16 * LDK * 2));
        }
        uint32_t bh[2][4], bl[2][4];
        #pragma unroll
        for (int g = 0; g < 2; g++) {
            ldm_x4(bh[g], aWhi + koff + (uint32_t)(g * 16 * LDK * 2));
            ldm_x4(bl[g], aWlo + koff + (uint32_t)(g * 16 * LDK * 2));
        }
        // b fragment for n-frag nf: regs {bh[nf/2][(nf&1)*2], bh[nf/2][(nf&1)*2+1]}
        #pragma unroll
        for (int mf = 0; mf < 4; mf++) {
            #pragma unroll
            for (int nf = 0; nf < 4; nf++) {
                const int g = nf >> 1, h = (nf & 1) * 2;
                mma16816(acc[mf][nf], ah[mf], bh[g][h], bh[g][h + 1]);
                mma16816(acc[mf][nf], ah[mf], bl[g][h], bl[g][h + 1]);
                mma16816(acc[mf][nf], al[mf], bh[g][h], bh[g][h + 1]);
            }
        }
    }

    // --- epilogue: bias + log_sigmoid, direct register->global stores ---
    const int r_base = row0 + wm * 64 + (lane >> 2);
    const int c_base = wn * 32 + (lane & 3) * 2;
    #pragma unroll
    for (int mf = 0; mf < 4; mf++) {
        #pragma unroll
        for (int nf = 0; nf < 4; nf++) {
            const int c0 = c_base + nf * 8;
            float b0 = 0.f, b1 = 0.f;
            if (HASBIAS) { b0 = s_bias[c0]; b1 = s_bias[c0 + 1]; }
            #pragma unroll
            for (int half = 0; half < 2; half++) {   // rows r and r+8
                const int rg = r_base + mf * 16 + half * 8;
                float v0 = log_sigmoid(acc[mf][nf][half * 2 + 0] + b0);
                float v1 = log_sigmoid(acc[mf][nf][half * 2 + 1] + b1);
                if (OUTSPLIT) {
                    __nv_bfloat16 h0 = __float2bfloat16(v0);
                    __nv_bfloat16 h1 = __float2bfloat16(v1);
                    __nv_bfloat16 l0 = __float2bfloat16(v0 - __bfloat162float(h0));
                    __nv_bfloat16 l1 = __float2bfloat16(v1 - __bfloat162float(h1));
                    size_t u = ((size_t)rg * 128 + c0) >> 1;
                    reinterpret_cast<uint32_t*>(Chi)[u] = pack2(h0, h1);
                    reinterpret_cast<uint32_t*>(Clo)[u] = pack2(l0, l1);
                } else {
                    *reinterpret_cast<float2*>(Cf + (size_t)rg * 128 + c0) =
                        make_float2(v0, v1);
                }
            }
        }
    }
}

// ---------------- kernel: scan mask rows, build adjacency --------------------
__global__ void __launch_bounds__(256)
build_lists_kernel(const float* __restrict__ mask) {
    const int n   = blockIdx.x;
    const int tid = threadIdx.x;
    const float4* mrow = reinterpret_cast<const float4*>(mask + (size_t)n * N_EDGES);

    int local[16];
    int c = 0;
    for (int i = tid; i < N_EDGES / 4; i += 256) {
        float4 v = __ldcs(&mrow[i]);
        int e = i * 4;
        if (v.x != 0.0f) { if (c < 16) local[c] = e + 0; c++; }
        if (v.y != 0.0f) { if (c < 16) local[c] = e + 1; c++; }
        if (v.z != 0.0f) { if (c < 16) local[c] = e + 2; c++; }
        if (v.w != 0.0f) { if (c < 16) local[c] = e + 3; c++; }
    }
    c = min(c, 16);

    __shared__ int s_scan[256];
    s_scan[tid] = c;
    __syncthreads();
    #pragma unroll
    for (int off = 1; off < 256; off <<= 1) {
        int v = (tid >= off) ? s_scan[tid - off] : 0;
        __syncthreads();
        s_scan[tid] += v;
        __syncthreads();
    }
    int offset = s_scan[tid] - c;
    int total  = s_scan[255];

    for (int j = 0; j < c; j++) {
        int e   = local[j];
        int pos = offset + j;
        if (pos < NODE_CAP) g_node_edges[n * NODE_CAP + pos] = e;
        int q = atomicAdd(&g_edge_cnt[e], 1);
        if (q < EDGE_CAP) g_edge_nodes[e * EDGE_CAP + q] = n;
    }
    if (tid == 0) g_node_cnt[n] = min(total, NODE_CAP);
}

// ---------------- kernel: nodesum[n] = sum_{e in list(n)} s[e] ---------------
__global__ void __launch_bounds__(128)
node_sum_kernel() {
    const int n = blockIdx.x;
    const int d = threadIdx.x;
    const int cnt = g_node_cnt[n];
    const int* lst = &g_node_edges[n * NODE_CAP];

    float a0 = 0.f, a1 = 0.f, a2 = 0.f, a3 = 0.f;
    int i = 0;
    for (; i + 4 <= cnt; i += 4) {
        int e0 = lst[i], e1 = lst[i + 1], e2 = lst[i + 2], e3 = lst[i + 3];
        a0 += g_s[(size_t)e0 * 128 + d];
        a1 += g_s[(size_t)e1 * 128 + d];
        a2 += g_s[(size_t)e2 * 128 + d];
        a3 += g_s[(size_t)e3 * 128 + d];
    }
    for (; i < cnt; i++) a0 += g_s[(size_t)lst[i] * 128 + d];
    g_nodesum[n * 128 + d] = (a0 + a1) + (a2 + a3);
}

// ---------------- kernel: agg + concat ---------------------------------------
__global__ void __launch_bounds__(128)
edge_gather_kernel(const float* __restrict__ feature) {
    const int e   = blockIdx.x;
    const int tid = threadIdx.x;

    __shared__ int sl[EDGE_CAP];
    __shared__ int ss[EDGE_CAP];
    const int cnt = min(g_edge_cnt[e], EDGE_CAP);

    if (tid < cnt) sl[tid] = g_edge_nodes[e * EDGE_CAP + tid];
    __syncthreads();
    if (tid < cnt) {
        int v = sl[tid];
        int r = 0;
        for (int j = 0; j < cnt; j++) r += (sl[j] < v);
        ss[r] = v;   // node ids unique per edge -> ranks distinct
    }
    __syncthreads();

    float acc = -g_s[(size_t)e * 128 + tid];
    for (int i = 0; i < cnt; i++)
        acc += g_nodesum[ss[i] * 128 + tid];
    g_aggcat[(size_t)e * D_CAT + tid] = acc;
    if (tid < D_FEAT)
        g_aggcat[(size_t)e * D_CAT + 128 + tid] = feature[(size_t)e * D_FEAT + tid];
}

// ---------------- launch -----------------------------------------------------
extern "C" void kernel_launch(void* const* d_in, const int* in_sizes, int n_in,
                              void* d_out, int out_size) {
    const float* state   = (const float*)d_in[0];
    const float* feature = (const float*)d_in[1];
    const float* mask    = (const float*)d_in[2];
    // d_in[3] = mask_transpose (unused: exactly mask.T)
    const float* W1_m    = (const float*)d_in[4];
    const float* b1_m    = (const float*)d_in[5];
    const float* W2_m    = (const float*)d_in[6];
    const float* W1_a    = (const float*)d_in[7];
    const float* b1_a    = (const float*)d_in[8];
    const float* W2_a    = (const float*)d_in[9];
    float* out = (float*)d_out;

    const int SMEM128 = 512 + 4 * (128 * 136 * 2);   // 139,776 B
    const int SMEM160 = 512 + 4 * (128 * 168 * 2);   // 172,544 B
    cudaFuncSetAttribute((const void*)gemm_mma_kernel<128, false, true, true>,
                         cudaFuncAttributeMaxDynamicSharedMemorySize, SMEM128);
    cudaFuncSetAttribute((const void*)gemm_mma_kernel<128, true, false, false>,
                         cudaFuncAttributeMaxDynamicSharedMemorySize, SMEM128);
    cudaFuncSetAttribute((const void*)gemm_mma_kernel<160, false, true, true>,
                         cudaFuncAttributeMaxDynamicSharedMemorySize, SMEM160);

    float *d_s = nullptr, *d_aggcat = nullptr;
    __nv_bfloat16 *d_hhi = nullptr, *d_hlo = nullptr;
    __nv_bfloat16 *d_w1mh = nullptr, *d_w1ml = nullptr, *d_w2mh = nullptr, *d_w2ml = nullptr;
    __nv_bfloat16 *d_w1ah = nullptr, *d_w1al = nullptr, *d_w2ah = nullptr, *d_w2al = nullptr;
    cudaGetSymbolAddress((void**)&d_s, g_s);
    cudaGetSymbolAddress((void**)&d_aggcat, g_aggcat);
    cudaGetSymbolAddress((void**)&d_hhi, g_h_hi);
    cudaGetSymbolAddress((void**)&d_hlo, g_h_lo);
    cudaGetSymbolAddress((void**)&d_w1mh, g_w1m_hi);
    cudaGetSymbolAddress((void**)&d_w1ml, g_w1m_lo);
    cudaGetSymbolAddress((void**)&d_w2mh, g_w2m_hi);
    cudaGetSymbolAddress((void**)&d_w2ml, g_w2m_lo);
    cudaGetSymbolAddress((void**)&d_w1ah, g_w1a_hi);
    cudaGetSymbolAddress((void**)&d_w1al, g_w1a_lo);
    cudaGetSymbolAddress((void**)&d_w2ah, g_w2a_hi);
    cudaGetSymbolAddress((void**)&d_w2al, g_w2a_lo);

    const int GB = N_EDGES / 128;   // 256 CTAs per GEMM

    zero_edge_cnt_kernel<<<N_EDGES / 256, 256>>>();
    prep_weights_kernel<<<(128 * 160 + 255) / 256, 256>>>(W1_m, W2_m, W1_a, W2_a);

    // memory MLP (HMMA bf16-split)
    gemm_mma_kernel<128, false, true, true><<<GB, 256, SMEM128>>>(
        state, nullptr, nullptr, d_w1mh, d_w1ml, b1_m, nullptr, d_hhi, d_hlo);
    gemm_mma_kernel<128, true, false, false><<<GB, 256, SMEM128>>>(
        nullptr, d_hhi, d_hlo, d_w2mh, d_w2ml, nullptr, d_s, nullptr, nullptr);

    // sparse bipartite aggregation (mask read once; transpose never touched)
    build_lists_kernel<<<N_NODES, 256>>>(mask);
    node_sum_kernel<<<N_NODES, 128>>>();
    edge_gather_kernel<<<N_EDGES, 128>>>(feature);

    // aggregation MLP
    gemm_mma_kernel<160, false, true, true><<<GB, 256, SMEM160>>>(
        d_aggcat, nullptr, nullptr, d_w1ah, d_w1al, b1_a, nullptr, d_hhi, d_hlo);
    gemm_mma_kernel<128, true, false, false><<<GB, 256, SMEM128>>>(
        nullptr, d_hhi, d_hlo, d_w2ah, d_w2al, nullptr, out, nullptr, nullptr);
}

// round 13
// speedup vs baseline: 1.8700x; 1.2456x over previous
#include <cuda_runtime.h>
#include <cuda_bf16.h>
#include <cstdint>

// Problem constants
#define N_EDGES   32768
#define N_NODES   2048
#define D_FEAT    32
#define D_CAT     160
#define NODE_CAP  512
#define EDGE_CAP  64

// ---------------- scratch (static device globals; no allocation) -------------
__device__ float g_s[N_EDGES * 128];              // s = memory MLP output (fp32)
__device__ float g_nodesum[N_NODES * 128];        // mask @ s
__device__ __nv_bfloat16 g_agg_hi[N_EDGES * D_CAT];  // pre-split [agg | feature]
__device__ __nv_bfloat16 g_agg_lo[N_EDGES * D_CAT];
__device__ __nv_bfloat16 g_w1m_hi[128 * 128], g_w1m_lo[128 * 128];
__device__ __nv_bfloat16 g_w2m_hi[128 * 128], g_w2m_lo[128 * 128];
__device__ __nv_bfloat16 g_w1a_hi[128 * 160], g_w1a_lo[128 * 160];
__device__ __nv_bfloat16 g_w2a_hi[128 * 128], g_w2a_lo[128 * 128];
__device__ int   g_node_cnt[N_NODES];
__device__ int   g_node_edges[N_NODES * NODE_CAP];
__device__ int   g_edge_cnt[N_EDGES];
__device__ int   g_edge_nodes[N_EDGES * EDGE_CAP];

// ---------------- small helpers ----------------------------------------------
__device__ __forceinline__ float log_sigmoid(float x) {
    return fminf(x, 0.0f) - log1pf(__expf(-fabsf(x)));
}

__device__ __forceinline__ uint32_t smem_u32(const void* p) {
    uint32_t a;
    asm("{ .reg .u64 t; cvta.to.shared.u64 t, %1; cvt.u32.u64 %0, t; }" : "=r"(a) : "l"(p));
    return a;
}

__device__ __forceinline__ uint32_t pack2(__nv_bfloat16 a, __nv_bfloat16 b) {
    __nv_bfloat162 p;
    p.x = a; p.y = b;
    return *reinterpret_cast<uint32_t*>(&p);
}

__device__ __forceinline__ void ldm_x4(uint32_t* r, uint32_t addr) {
    asm volatile("ldmatrix.sync.aligned.m8n8.x4.shared.b16 {%0,%1,%2,%3}, [%4];"
                 : "=r"(r[0]), "=r"(r[1]), "=r"(r[2]), "=r"(r[3]) : "r"(addr));
}

__device__ __forceinline__ void mma16816(float* c, const uint32_t* a, uint32_t b0, uint32_t b1) {
    asm volatile("mma.sync.aligned.m16n8k16.row.col.f32.bf16.bf16.f32 "
                 "{%0,%1,%2,%3}, {%4,%5,%6,%7}, {%8,%9}, {%0,%1,%2,%3};"
                 : "+f"(c[0]), "+f"(c[1]), "+f"(c[2]), "+f"(c[3])
                 : "r"(a[0]), "r"(a[1]), "r"(a[2]), "r"(a[3]), "r"(b0), "r"(b1));
}

__device__ __forceinline__ void cp16(uint32_t dst, const void* src) {
    asm volatile("cp.async.cg.shared.global [%0], [%1], 16;" :: "r"(dst), "l"(src));
}
__device__ __forceinline__ void cp_commit_wait() {
    asm volatile("cp.async.commit_group;" ::: "memory");
    asm volatile("cp.async.wait_group 0;" ::: "memory");
}

// bf16-split 3-product MMA over one K panel.
// Warp tile 32x32: 2 m-frags x 4 n-frags, standard m16n8k16 fragment layouts.
template <int NK>
__device__ __forceinline__ void mma_block(
    uint32_t aHi, uint32_t aLo, uint32_t bHi, uint32_t bLo,
    uint32_t ldkB, float (*acc)[4][4])
{
    #pragma unroll
    for (int ks = 0; ks < NK; ks++) {
        const uint32_t koff = (uint32_t)ks * 32;
        uint32_t ah[2][4], al[2][4], bh[2][4], bl[2][4];
        #pragma unroll
        for (int mf = 0; mf < 2; mf++) {
            ldm_x4(ah[mf], aHi + koff + (uint32_t)mf * 16 * ldkB);
            ldm_x4(al[mf], aLo + koff + (uint32_t)mf * 16 * ldkB);
        }
        #pragma unroll
        for (int g = 0; g < 2; g++) {
            ldm_x4(bh[g], bHi + koff + (uint32_t)g * 16 * ldkB);
            ldm_x4(bl[g], bLo + koff + (uint32_t)g * 16 * ldkB);
        }
        #pragma unroll
        for (int mf = 0; mf < 2; mf++) {
            #pragma unroll
            for (int nf = 0; nf < 4; nf++) {
                const int g = nf >> 1, h = (nf & 1) * 2;
                mma16816(acc[mf][nf], ah[mf], bh[g][h], bh[g][h + 1]);
                mma16816(acc[mf][nf], ah[mf], bl[g][h], bl[g][h + 1]);
                mma16816(acc[mf][nf], al[mf], bh[g][h], bh[g][h + 1]);
            }
        }
    }
}

// ---------------- kernel: zero edge counters ---------------------------------
__global__ void zero_edge_cnt_kernel() {
    int i = blockIdx.x * blockDim.x + threadIdx.x;
    if (i < N_EDGES) g_edge_cnt[i] = 0;
}

// ---------------- kernel: split weights into bf16 hi/lo ----------------------
__global__ void prep_weights_kernel(const float* __restrict__ w1m,
                                    const float* __restrict__ w2m,
                                    const float* __restrict__ w1a,
                                    const float* __restrict__ w2a) {
    int i = blockIdx.x * blockDim.x + threadIdx.x;
    if (i < 128 * 128) {
        float v = w1m[i];
        __nv_bfloat16 h = __float2bfloat16(v);
        g_w1m_hi[i] = h; g_w1m_lo[i] = __float2bfloat16(v - __bfloat162float(h));
        v = w2m[i]; h = __float2bfloat16(v);
        g_w2m_hi[i] = h; g_w2m_lo[i] = __float2bfloat16(v - __bfloat162float(h));
        v = w2a[i]; h = __float2bfloat16(v);
        g_w2a_hi[i] = h; g_w2a_lo[i] = __float2bfloat16(v - __bfloat162float(h));
    }
    if (i < 128 * 160) {
        float v = w1a[i];
        __nv_bfloat16 h = __float2bfloat16(v);
        g_w1a_hi[i] = h; g_w1a_lo[i] = __float2bfloat16(v - __bfloat162float(h));
    }
}

// ---------------- kernel: fused 2-layer MLP (HMMA bf16-split) ----------------
// out[64-tile,128] = ls( ls( A[tile,K1] @ W1[128,K1]^T + b1 ) @ W2[128,128]^T )
// Phase 1 writes h (split bf16) into the A smem buffers; W2 replaces W1 in the
// W buffers via cp.async during the phase boundary. Grid = 512 (64-row tiles),
// 8 warps = 2(M) x 4(N), 32x32 warp tiles.
template <int K1, bool ACVT>
__global__ void __launch_bounds__(256, 2)
fused_mlp_kernel(const float* __restrict__ Af,
                 const __nv_bfloat16* __restrict__ Ahi,
                 const __nv_bfloat16* __restrict__ Alo,
                 const __nv_bfloat16* __restrict__ W1hi,
                 const __nv_bfloat16* __restrict__ W1lo,
                 const float* __restrict__ b1,
                 const __nv_bfloat16* __restrict__ W2hi,
                 const __nv_bfloat16* __restrict__ W2lo,
                 float* __restrict__ Cout) {
    extern __shared__ char sm[];
    constexpr int LDK1 = K1 + 8;
    constexpr int LDK2 = 136;
    constexpr int TA = 64 * LDK1 * 2;     // A/h buffer bytes (h needs 64*136*2 <= TA)
    constexpr int TW = 128 * LDK1 * 2;
    float*         s_bias = reinterpret_cast<float*>(sm);
    __nv_bfloat16* sAhi = reinterpret_cast<__nv_bfloat16*>(sm + 512);
    __nv_bfloat16* sAlo = reinterpret_cast<__nv_bfloat16*>(sm + 512 + TA);
    __nv_bfloat16* sWhi = reinterpret_cast<__nv_bfloat16*>(sm + 512 + 2 * TA);
    __nv_bfloat16* sWlo = reinterpret_cast<__nv_bfloat16*>(sm + 512 + 2 * TA + TW);

    const int tid  = threadIdx.x;
    const int wid  = tid >> 5;
    const int lane = tid & 31;
    const int row0 = blockIdx.x * 64;
    const uint32_t uAhi = smem_u32(sAhi), uAlo = smem_u32(sAlo);
    const uint32_t uWhi = smem_u32(sWhi), uWlo = smem_u32(sWlo);

    if (tid < 128) s_bias[tid] = b1[tid];

    // --- W1 via cp.async ---
    {
        constexpr int NC = 128 * (K1 / 8);
        for (int idx = tid; idx < NC; idx += 256) {
            int row = idx / (K1 / 8);
            int ko  = (idx % (K1 / 8)) * 8;
            uint32_t d = (uint32_t)(row * LDK1 + ko) * 2;
            cp16(uWhi + d, W1hi + (size_t)row * K1 + ko);
            cp16(uWlo + d, W1lo + (size_t)row * K1 + ko);
        }
    }
    // --- A tile ---
    if (ACVT) {
        constexpr int NV = 64 * (K1 / 4);
        const float4* a4 = reinterpret_cast<const float4*>(Af + (size_t)row0 * K1);
        for (int idx = tid; idx < NV; idx += 256) {
            int row = idx / (K1 / 4);
            int k0  = (idx % (K1 / 4)) * 4;
            float4 v = a4[idx];
            __nv_bfloat16 h0 = __float2bfloat16(v.x), h1 = __float2bfloat16(v.y);
            __nv_bfloat16 h2 = __float2bfloat16(v.z), h3 = __float2bfloat16(v.w);
            __nv_bfloat16 l0 = __float2bfloat16(v.x - __bfloat162float(h0));
            __nv_bfloat16 l1 = __float2bfloat16(v.y - __bfloat162float(h1));
            __nv_bfloat16 l2 = __float2bfloat16(v.z - __bfloat162float(h2));
            __nv_bfloat16 l3 = __float2bfloat16(v.w - __bfloat162float(h3));
            uint32_t* ph = reinterpret_cast<uint32_t*>(&sAhi[row * LDK1 + k0]);
            uint32_t* pl = reinterpret_cast<uint32_t*>(&sAlo[row * LDK1 + k0]);
            ph[0] = pack2(h0, h1); ph[1] = pack2(h2, h3);
            pl[0] = pack2(l0, l1); pl[1] = pack2(l2, l3);
        }
    } else {
        constexpr int NC = 64 * (K1 / 8);
        for (int idx = tid; idx < NC; idx += 256) {
            int row = idx / (K1 / 8);
            int ko  = (idx % (K1 / 8)) * 8;
            uint32_t d = (uint32_t)(row * LDK1 + ko) * 2;
            cp16(uAhi + d, Ahi + (size_t)(row0 + row) * K1 + ko);
            cp16(uAlo + d, Alo + (size_t)(row0 + row) * K1 + ko);
        }
    }
    cp_commit_wait();
    __syncthreads();

    const int wm = wid >> 2;         // 0..1 -> 32-row half
    const int wn = wid & 3;          // 0..3 -> 32-col quarter
    const int rl = lane >> 2;        // 0..7
    const int cl = (lane & 3) * 2;   // 0,2,4,6

    // fragment addresses (A: m16k16 x4 pattern; B: two n-halves per x4)
    const int arow = wm * 32 + (lane & 7) + ((lane >> 3) & 1) * 8;
    const int acol = (lane >> 4) * 8;
    const int brow = wn * 32 + (lane & 7) + ((lane >> 4) & 1) * 8;
    const int bcol = ((lane >> 3) & 1) * 8;

    float acc[2][4][4];
    #pragma unroll
    for (int i = 0; i < 2; i++)
        #pragma unroll
        for (int j = 0; j < 4; j++)
            #pragma unroll
            for (int e = 0; e < 4; e++) acc[i][j][e] = 0.0f;

    // ---- phase 1: h = A @ W1^T ----
    mma_block<K1 / 16>(
        uAhi + (uint32_t)(arow * LDK1 + acol) * 2,
        uAlo + (uint32_t)(arow * LDK1 + acol) * 2,
        uWhi + (uint32_t)(brow * LDK1 + bcol) * 2,
        uWlo + (uint32_t)(brow * LDK1 + bcol) * 2,
        (uint32_t)LDK1 * 2, acc);

    __syncthreads();   // all phase-1 reads of sA/sW complete

    // --- W2 via cp.async (overwrites W buffers, stride LDK2) ---
    {
        constexpr int NC = 128 * 16;   // K2/8 = 16
        for (int idx = tid; idx < NC; idx += 256) {
            int row = idx >> 4;
            int ko  = (idx & 15) * 8;
            uint32_t d = (uint32_t)(row * LDK2 + ko) * 2;
            cp16(uWhi + d, W2hi + (size_t)row * 128 + ko);
            cp16(uWlo + d, W2lo + (size_t)row * 128 + ko);
        }
    }
    // --- bias + ls, split h into A buffers (stride LDK2) ---
    #pragma unroll
    for (int mf = 0; mf < 2; mf++) {
        #pragma unroll
        for (int nf = 0; nf < 4; nf++) {
            const int c0 = wn * 32 + nf * 8 + cl;
            const float b0 = s_bias[c0], b1v = s_bias[c0 + 1];
            #pragma unroll
            for (int half = 0; half < 2; half++) {
                const int row = wm * 32 + mf * 16 + rl + half * 8;
                float v0 = log_sigmoid(acc[mf][nf][half * 2 + 0] + b0);
                float v1 = log_sigmoid(acc[mf][nf][half * 2 + 1] + b1v);
                __nv_bfloat16 h0 = __float2bfloat16(v0);
                __nv_bfloat16 h1 = __float2bfloat16(v1);
                __nv_bfloat16 l0 = __float2bfloat16(v0 - __bfloat162float(h0));
                __nv_bfloat16 l1 = __float2bfloat16(v1 - __bfloat162float(h1));
                *reinterpret_cast<uint32_t*>(&sAhi[row * LDK2 + c0]) = pack2(h0, h1);
                *reinterpret_cast<uint32_t*>(&sAlo[row * LDK2 + c0]) = pack2(l0, l1);
            }
        }
    }
    cp_commit_wait();
    __syncthreads();

    #pragma unroll
    for (int i = 0; i < 2; i++)
        #pragma unroll
        for (int j = 0; j < 4; j++)
            #pragma unroll
            for (int e = 0; e < 4; e++) acc[i][j][e] = 0.0f;

    // ---- phase 2: out = ls( h @ W2^T ) ----
    mma_block<8>(
        uAhi + (uint32_t)(arow * LDK2 + acol) * 2,
        uAlo + (uint32_t)(arow * LDK2 + acol) * 2,
        uWhi + (uint32_t)(brow * LDK2 + bcol) * 2,
        uWlo + (uint32_t)(brow * LDK2 + bcol) * 2,
        (uint32_t)LDK2 * 2, acc);

    #pragma unroll
    for (int mf = 0; mf < 2; mf++) {
        #pragma unroll
        for (int nf = 0; nf < 4; nf++) {
            const int c0 = wn * 32 + nf * 8 + cl;
            #pragma unroll
            for (int half = 0; half < 2; half++) {
                const int rg = row0 + wm * 32 + mf * 16 + rl + half * 8;
                float v0 = log_sigmoid(acc[mf][nf][half * 2 + 0]);
                float v1 = log_sigmoid(acc[mf][nf][half * 2 + 1]);
                *reinterpret_cast<float2*>(Cout + (size_t)rg * 128 + c0) =
                    make_float2(v0, v1);
            }
        }
    }
}

// ---------------- kernel: scan mask rows, build adjacency --------------------
__global__ void __launch_bounds__(256)
build_lists_kernel(const float* __restrict__ mask) {
    const int n   = blockIdx.x;
    const int tid = threadIdx.x;
    const float4* mrow = reinterpret_cast<const float4*>(mask + (size_t)n * N_EDGES);

    int local[16];
    int c = 0;
    for (int i = tid; i < N_EDGES / 4; i += 256) {
        float4 v = __ldcs(&mrow[i]);
        int e = i * 4;
        if (v.x != 0.0f) { if (c < 16) local[c] = e + 0; c++; }
        if (v.y != 0.0f) { if (c < 16) local[c] = e + 1; c++; }
        if (v.z != 0.0f) { if (c < 16) local[c] = e + 2; c++; }
        if (v.w != 0.0f) { if (c < 16) local[c] = e + 3; c++; }
    }
    c = min(c, 16);

    __shared__ int s_scan[256];
    s_scan[tid] = c;
    __syncthreads();
    #pragma unroll
    for (int off = 1; off < 256; off <<= 1) {
        int v = (tid >= off) ? s_scan[tid - off] : 0;
        __syncthreads();
        s_scan[tid] += v;
        __syncthreads();
    }
    int offset = s_scan[tid] - c;
    int total  = s_scan[255];

    for (int j = 0; j < c; j++) {
        int e   = local[j];
        int pos = offset + j;
        if (pos < NODE_CAP) g_node_edges[n * NODE_CAP + pos] = e;
        int q = atomicAdd(&g_edge_cnt[e], 1);
        if (q < EDGE_CAP) g_edge_nodes[e * EDGE_CAP + q] = n;
    }
    if (tid == 0) g_node_cnt[n] = min(total, NODE_CAP);
}

// ---------------- kernel: nodesum[n] = sum_{e in list(n)} s[e] ---------------
__global__ void __launch_bounds__(128)
node_sum_kernel() {
    const int n = blockIdx.x;
    const int d = threadIdx.x;
    const int cnt = g_node_cnt[n];
    const int* lst = &g_node_edges[n * NODE_CAP];

    float a0 = 0.f, a1 = 0.f, a2 = 0.f, a3 = 0.f;
    int i = 0;
    for (; i + 4 <= cnt; i += 4) {
        int e0 = lst[i], e1 = lst[i + 1], e2 = lst[i + 2], e3 = lst[i + 3];
        a0 += g_s[(size_t)e0 * 128 + d];
        a1 += g_s[(size_t)e1 * 128 + d];
        a2 += g_s[(size_t)e2 * 128 + d];
        a3 += g_s[(size_t)e3 * 128 + d];
    }
    for (; i < cnt; i++) a0 += g_s[(size_t)lst[i] * 128 + d];
    g_nodesum[n * 128 + d] = (a0 + a1) + (a2 + a3);
}

// ---------------- kernel: agg + concat, written pre-split bf16 ---------------
__global__ void __launch_bounds__(128)
edge_gather_kernel(const float* __restrict__ feature) {
    const int e   = blockIdx.x;
    const int tid = threadIdx.x;

    __shared__ int sl[EDGE_CAP];
    __shared__ int ss[EDGE_CAP];
    const int cnt = min(g_edge_cnt[e], EDGE_CAP);

    if (tid < cnt) sl[tid] = g_edge_nodes[e * EDGE_CAP + tid];
    __syncthreads();
    if (tid < cnt) {
        int v = sl[tid];
        int r = 0;
        for (int j = 0; j < cnt; j++) r += (sl[j] < v);
        ss[r] = v;   // node ids unique per edge -> ranks distinct
    }
    __syncthreads();

    float acc = -g_s[(size_t)e * 128 + tid];
    for (int i = 0; i < cnt; i++)
        acc += g_nodesum[ss[i] * 128 + tid];
    {
        __nv_bfloat16 h = __float2bfloat16(acc);
        g_agg_hi[(size_t)e * D_CAT + tid] = h;
        g_agg_lo[(size_t)e * D_CAT + tid] = __float2bfloat16(acc - __bfloat162float(h));
    }
    if (tid < D_FEAT) {
        float f = feature[(size_t)e * D_FEAT + tid];
        __nv_bfloat16 h = __float2bfloat16(f);
        g_agg_hi[(size_t)e * D_CAT + 128 + tid] = h;
        g_agg_lo[(size_t)e * D_CAT + 128 + tid] = __float2bfloat16(f - __bfloat162float(h));
    }
}

// ---------------- launch -----------------------------------------------------
extern "C" void kernel_launch(void* const* d_in, const int* in_sizes, int n_in,
                              void* d_out, int out_size) {
    const float* state   = (const float*)d_in[0];
    const float* feature = (const float*)d_in[1];
    const float* mask    = (const float*)d_in[2];
    // d_in[3] = mask_transpose (unused: exactly mask.T)
    const float* W1_m    = (const float*)d_in[4];
    const float* b1_m    = (const float*)d_in[5];
    const float* W2_m    = (const float*)d_in[6];
    const float* W1_a    = (const float*)d_in[7];
    const float* b1_a    = (const float*)d_in[8];
    const float* W2_a    = (const float*)d_in[9];
    float* out = (float*)d_out;

    // smem: 512 + 2*A(64*LDK1*2) + 2*W(128*LDK1*2)
    const int SMEM_A = 512 + 2 * (64 * 136 * 2) + 2 * (128 * 136 * 2);  // 104,960
    const int SMEM_B = 512 + 2 * (64 * 168 * 2) + 2 * (128 * 168 * 2);  // 129,536
    cudaFuncSetAttribute((const void*)fused_mlp_kernel<128, true>,
                         cudaFuncAttributeMaxDynamicSharedMemorySize, SMEM_A);
    cudaFuncSetAttribute((const void*)fused_mlp_kernel<160, false>,
                         cudaFuncAttributeMaxDynamicSharedMemorySize, SMEM_B);

    float* d_s = nullptr;
    __nv_bfloat16 *d_agg_hi = nullptr, *d_agg_lo = nullptr;
    __nv_bfloat16 *d_w1mh = nullptr, *d_w1ml = nullptr, *d_w2mh = nullptr, *d_w2ml = nullptr;
    __nv_bfloat16 *d_w1ah = nullptr, *d_w1al = nullptr, *d_w2ah = nullptr, *d_w2al = nullptr;
    cudaGetSymbolAddress((void**)&d_s, g_s);
    cudaGetSymbolAddress((void**)&d_agg_hi, g_agg_hi);
    cudaGetSymbolAddress((void**)&d_agg_lo, g_agg_lo);
    cudaGetSymbolAddress((void**)&d_w1mh, g_w1m_hi);
    cudaGetSymbolAddress((void**)&d_w1ml, g_w1m_lo);
    cudaGetSymbolAddress((void**)&d_w2mh, g_w2m_hi);
    cudaGetSymbolAddress((void**)&d_w2ml, g_w2m_lo);
    cudaGetSymbolAddress((void**)&d_w1ah, g_w1a_hi);
    cudaGetSymbolAddress((void**)&d_w1al, g_w1a_lo);
    cudaGetSymbolAddress((void**)&d_w2ah, g_w2a_hi);
    cudaGetSymbolAddress((void**)&d_w2al, g_w2a_lo);

    const int GB = N_EDGES / 64;   // 512 CTAs per fused MLP

    zero_edge_cnt_kernel<<<N_EDGES / 256, 256>>>();
    prep_weights_kernel<<<(128 * 160 + 255) / 256, 256>>>(W1_m, W2_m, W1_a, W2_a);

    // memory MLP (fused 2 layers): s = ls(ls(state@W1m^T+b1m)@W2m^T)
    fused_mlp_kernel<128, true><<<GB, 256, SMEM_A>>>(
        state, nullptr, nullptr, d_w1mh, d_w1ml, b1_m, d_w2mh, d_w2ml, d_s);

    // sparse bipartite aggregation (mask read once; transpose never touched)
    build_lists_kernel<<<N_NODES, 256>>>(mask);
    node_sum_kernel<<<N_NODES, 128>>>();
    edge_gather_kernel<<<N_EDGES, 128>>>(feature);

    // aggregation MLP (fused 2 layers): out = ls(ls(agg@W1a^T+b1a)@W2a^T)
    fused_mlp_kernel<160, false><<<GB, 256, SMEM_B>>>(
        nullptr, d_agg_hi, d_agg_lo, d_w1ah, d_w1al, b1_a, d_w2ah, d_w2al, out);
}

// round 14
// speedup vs baseline: 1.8759x; 1.0032x over previous
#include <cuda_runtime.h>
#include <cuda_bf16.h>
#include <cstdint>

// Problem constants
#define N_EDGES   32768
#define N_NODES   2048
#define D_FEAT    32
#define D_CAT     160
#define NODE_CAP  512
#define EDGE_CAP  64

// ---------------- scratch (static device globals; no allocation) -------------
__device__ float g_s[N_EDGES * 128];              // s = memory MLP output (fp32)
__device__ float g_nodesum[N_NODES * 128];        // mask @ s
__device__ __nv_bfloat16 g_agg_hi[N_EDGES * D_CAT];  // pre-split [agg | feature]
__device__ __nv_bfloat16 g_agg_lo[N_EDGES * D_CAT];
__device__ __nv_bfloat16 g_w1m_hi[128 * 128], g_w1m_lo[128 * 128];
__device__ __nv_bfloat16 g_w2m_hi[128 * 128], g_w2m_lo[128 * 128];
__device__ __nv_bfloat16 g_w1a_hi[128 * 160], g_w1a_lo[128 * 160];
__device__ __nv_bfloat16 g_w2a_hi[128 * 128], g_w2a_lo[128 * 128];
__device__ int   g_node_cnt[N_NODES];
__device__ int   g_node_edges[N_NODES * NODE_CAP];
__device__ int   g_edge_cnt[N_EDGES];
__device__ int   g_edge_nodes[N_EDGES * EDGE_CAP];

// ---------------- small helpers ----------------------------------------------
__device__ __forceinline__ float log_sigmoid(float x) {
    return fminf(x, 0.0f) - log1pf(__expf(-fabsf(x)));
}

__device__ __forceinline__ uint32_t smem_u32(const void* p) {
    uint32_t a;
    asm("{ .reg .u64 t; cvta.to.shared.u64 t, %1; cvt.u32.u64 %0, t; }" : "=r"(a) : "l"(p));
    return a;
}

__device__ __forceinline__ uint32_t pack2(__nv_bfloat16 a, __nv_bfloat16 b) {
    __nv_bfloat162 p;
    p.x = a; p.y = b;
    return *reinterpret_cast<uint32_t*>(&p);
}

__device__ __forceinline__ void ldm_x4(uint32_t* r, uint32_t addr) {
    asm volatile("ldmatrix.sync.aligned.m8n8.x4.shared.b16 {%0,%1,%2,%3}, [%4];"
                 : "=r"(r[0]), "=r"(r[1]), "=r"(r[2]), "=r"(r[3]) : "r"(addr));
}

__device__ __forceinline__ void mma16816(float* c, const uint32_t* a, uint32_t b0, uint32_t b1) {
    asm volatile("mma.sync.aligned.m16n8k16.row.col.f32.bf16.bf16.f32 "
                 "{%0,%1,%2,%3}, {%4,%5,%6,%7}, {%8,%9}, {%0,%1,%2,%3};"
                 : "+f"(c[0]), "+f"(c[1]), "+f"(c[2]), "+f"(c[3])
                 : "r"(a[0]), "r"(a[1]), "r"(a[2]), "r"(a[3]), "r"(b0), "r"(b1));
}

__device__ __forceinline__ void cp16(uint32_t dst, const void* src) {
    asm volatile("cp.async.cg.shared.global [%0], [%1], 16;" :: "r"(dst), "l"(src));
}
__device__ __forceinline__ void cp_commit_wait() {
    asm volatile("cp.async.commit_group;" ::: "memory");
    asm volatile("cp.async.wait_group 0;" ::: "memory");
}

// bf16-split 3-product MMA over one K panel.
// Warp tile 32x32: 2 m-frags x 4 n-frags, standard m16n8k16 fragment layouts.
template <int NK>
__device__ __forceinline__ void mma_block(
    uint32_t aHi, uint32_t aLo, uint32_t bHi, uint32_t bLo,
    uint32_t ldkB, float (*acc)[4][4])
{
    #pragma unroll
    for (int ks = 0; ks < NK; ks++) {
        const uint32_t koff = (uint32_t)ks * 32;
        uint32_t ah[2][4], al[2][4], bh[2][4], bl[2][4];
        #pragma unroll
        for (int mf = 0; mf < 2; mf++) {
            ldm_x4(ah[mf], aHi + koff + (uint32_t)mf * 16 * ldkB);
            ldm_x4(al[mf], aLo + koff + (uint32_t)mf * 16 * ldkB);
        }
        #pragma unroll
        for (int g = 0; g < 2; g++) {
            ldm_x4(bh[g], bHi + koff + (uint32_t)g * 16 * ldkB);
            ldm_x4(bl[g], bLo + koff + (uint32_t)g * 16 * ldkB);
        }
        #pragma unroll
        for (int mf = 0; mf < 2; mf++) {
            #pragma unroll
            for (int nf = 0; nf < 4; nf++) {
                const int g = nf >> 1, h = (nf & 1) * 2;
                mma16816(acc[mf][nf], ah[mf], bh[g][h], bh[g][h + 1]);
                mma16816(acc[mf][nf], ah[mf], bl[g][h], bl[g][h + 1]);
                mma16816(acc[mf][nf], al[mf], bh[g][h], bh[g][h + 1]);
            }
        }
    }
}

// ---------------- kernel: zero edge counters ---------------------------------
__global__ void zero_edge_cnt_kernel() {
    int i = blockIdx.x * blockDim.x + threadIdx.x;
    if (i < N_EDGES) g_edge_cnt[i] = 0;
}

// ---------------- kernel: split weights into bf16 hi/lo ----------------------
__global__ void prep_weights_kernel(const float* __restrict__ w1m,
                                    const float* __restrict__ w2m,
                                    const float* __restrict__ w1a,
                                    const float* __restrict__ w2a) {
    int i = blockIdx.x * blockDim.x + threadIdx.x;
    if (i < 128 * 128) {
        float v = w1m[i];
        __nv_bfloat16 h = __float2bfloat16(v);
        g_w1m_hi[i] = h; g_w1m_lo[i] = __float2bfloat16(v - __bfloat162float(h));
        v = w2m[i]; h = __float2bfloat16(v);
        g_w2m_hi[i] = h; g_w2m_lo[i] = __float2bfloat16(v - __bfloat162float(h));
        v = w2a[i]; h = __float2bfloat16(v);
        g_w2a_hi[i] = h; g_w2a_lo[i] = __float2bfloat16(v - __bfloat162float(h));
    }
    if (i < 128 * 160) {
        float v = w1a[i];
        __nv_bfloat16 h = __float2bfloat16(v);
        g_w1a_hi[i] = h; g_w1a_lo[i] = __float2bfloat16(v - __bfloat162float(h));
    }
}

// ---------------- kernel: fused 2-layer MLP (HMMA bf16-split) ----------------
// out[64-tile,128] = ls( ls( A[tile,K1] @ W1[128,K1]^T + b1 ) @ W2[128,128]^T )
// Phase 1 writes h (split bf16) into the A smem buffers; W2 replaces W1 in the
// W buffers via cp.async during the phase boundary. Grid = 512 (64-row tiles),
// 8 warps = 2(M) x 4(N), 32x32 warp tiles.
template <int K1, bool ACVT>
__global__ void __launch_bounds__(256, 2)
fused_mlp_kernel(const float* __restrict__ Af,
                 const __nv_bfloat16* __restrict__ Ahi,
                 const __nv_bfloat16* __restrict__ Alo,
                 const __nv_bfloat16* __restrict__ W1hi,
                 const __nv_bfloat16* __restrict__ W1lo,
                 const float* __restrict__ b1,
                 const __nv_bfloat16* __restrict__ W2hi,
                 const __nv_bfloat16* __restrict__ W2lo,
                 float* __restrict__ Cout) {
    extern __shared__ char sm[];
    constexpr int LDK1 = K1 + 8;
    constexpr int LDK2 = 136;
    constexpr int TA = 64 * LDK1 * 2;     // A/h buffer bytes (h needs 64*136*2 <= TA)
    constexpr int TW = 128 * LDK1 * 2;
    float*         s_bias = reinterpret_cast<float*>(sm);
    __nv_bfloat16* sAhi = reinterpret_cast<__nv_bfloat16*>(sm + 512);
    __nv_bfloat16* sAlo = reinterpret_cast<__nv_bfloat16*>(sm + 512 + TA);
    __nv_bfloat16* sWhi = reinterpret_cast<__nv_bfloat16*>(sm + 512 + 2 * TA);
    __nv_bfloat16* sWlo = reinterpret_cast<__nv_bfloat16*>(sm + 512 + 2 * TA + TW);

    const int tid  = threadIdx.x;
    const int wid  = tid >> 5;
    const int lane = tid & 31;
    const int row0 = blockIdx.x * 64;
    const uint32_t uAhi = smem_u32(sAhi), uAlo = smem_u32(sAlo);
    const uint32_t uWhi = smem_u32(sWhi), uWlo = smem_u32(sWlo);

    if (tid < 128) s_bias[tid] = b1[tid];

    // --- W1 via cp.async ---
    {
        constexpr int NC = 128 * (K1 / 8);
        for (int idx = tid; idx < NC; idx += 256) {
            int row = idx / (K1 / 8);
            int ko  = (idx % (K1 / 8)) * 8;
            uint32_t d = (uint32_t)(row * LDK1 + ko) * 2;
            cp16(uWhi + d, W1hi + (size_t)row * K1 + ko);
            cp16(uWlo + d, W1lo + (size_t)row * K1 + ko);
        }
    }
    // --- A tile ---
    if (ACVT) {
        constexpr int NV = 64 * (K1 / 4);
        const float4* a4 = reinterpret_cast<const float4*>(Af + (size_t)row0 * K1);
        for (int idx = tid; idx < NV; idx += 256) {
            int row = idx / (K1 / 4);
            int k0  = (idx % (K1 / 4)) * 4;
            float4 v = a4[idx];
            __nv_bfloat16 h0 = __float2bfloat16(v.x), h1 = __float2bfloat16(v.y);
            __nv_bfloat16 h2 = __float2bfloat16(v.z), h3 = __float2bfloat16(v.w);
            __nv_bfloat16 l0 = __float2bfloat16(v.x - __bfloat162float(h0));
            __nv_bfloat16 l1 = __float2bfloat16(v.y - __bfloat162float(h1));
            __nv_bfloat16 l2 = __float2bfloat16(v.z - __bfloat162float(h2));
            __nv_bfloat16 l3 = __float2bfloat16(v.w - __bfloat162float(h3));
            uint32_t* ph = reinterpret_cast<uint32_t*>(&sAhi[row * LDK1 + k0]);
            uint32_t* pl = reinterpret_cast<uint32_t*>(&sAlo[row * LDK1 + k0]);
            ph[0] = pack2(h0, h1); ph[1] = pack2(h2, h3);
            pl[0] = pack2(l0, l1); pl[1] = pack2(l2, l3);
        }
    } else {
        constexpr int NC = 64 * (K1 / 8);
        for (int idx = tid; idx < NC; idx += 256) {
            int row = idx / (K1 / 8);
            int ko  = (idx % (K1 / 8)) * 8;
            uint32_t d = (uint32_t)(row * LDK1 + ko) * 2;
            cp16(uAhi + d, Ahi + (size_t)(row0 + row) * K1 + ko);
            cp16(uAlo + d, Alo + (size_t)(row0 + row) * K1 + ko);
        }
    }
    cp_commit_wait();
    __syncthreads();

    const int wm = wid >> 2;         // 0..1 -> 32-row half
    const int wn = wid & 3;          // 0..3 -> 32-col quarter
    const int rl = lane >> 2;        // 0..7
    const int cl = (lane & 3) * 2;   // 0,2,4,6

    // fragment addresses (A: m16k16 x4 pattern; B: two n-halves per x4)
    const int arow = wm * 32 + (lane & 7) + ((lane >> 3) & 1) * 8;
    const int acol = (lane >> 4) * 8;
    const int brow = wn * 32 + (lane & 7) + ((lane >> 4) & 1) * 8;
    const int bcol = ((lane >> 3) & 1) * 8;

    float acc[2][4][4];
    #pragma unroll
    for (int i = 0; i < 2; i++)
        #pragma unroll
        for (int j = 0; j < 4; j++)
            #pragma unroll
            for (int e = 0; e < 4; e++) acc[i][j][e] = 0.0f;

    // ---- phase 1: h = A @ W1^T ----
    mma_block<K1 / 16>(
        uAhi + (uint32_t)(arow * LDK1 + acol) * 2,
        uAlo + (uint32_t)(arow * LDK1 + acol) * 2,
        uWhi + (uint32_t)(brow * LDK1 + bcol) * 2,
        uWlo + (uint32_t)(brow * LDK1 + bcol) * 2,
        (uint32_t)LDK1 * 2, acc);

    __syncthreads();   // all phase-1 reads of sA/sW complete

    // --- W2 via cp.async (overwrites W buffers, stride LDK2) ---
    {
        constexpr int NC = 128 * 16;   // K2/8 = 16
        for (int idx = tid; idx < NC; idx += 256) {
            int row = idx >> 4;
            int ko  = (idx & 15) * 8;
            uint32_t d = (uint32_t)(row * LDK2 + ko) * 2;
            cp16(uWhi + d, W2hi + (size_t)row * 128 + ko);
            cp16(uWlo + d, W2lo + (size_t)row * 128 + ko);
        }
    }
    // --- bias + ls, split h into A buffers (stride LDK2) ---
    #pragma unroll
    for (int mf = 0; mf < 2; mf++) {
        #pragma unroll
        for (int nf = 0; nf < 4; nf++) {
            const int c0 = wn * 32 + nf * 8 + cl;
            const float b0 = s_bias[c0], b1v = s_bias[c0 + 1];
            #pragma unroll
            for (int half = 0; half < 2; half++) {
                const int row = wm * 32 + mf * 16 + rl + half * 8;
                float v0 = log_sigmoid(acc[mf][nf][half * 2 + 0] + b0);
                float v1 = log_sigmoid(acc[mf][nf][half * 2 + 1] + b1v);
                __nv_bfloat16 h0 = __float2bfloat16(v0);
                __nv_bfloat16 h1 = __float2bfloat16(v1);
                __nv_bfloat16 l0 = __float2bfloat16(v0 - __bfloat162float(h0));
                __nv_bfloat16 l1 = __float2bfloat16(v1 - __bfloat162float(h1));
                *reinterpret_cast<uint32_t*>(&sAhi[row * LDK2 + c0]) = pack2(h0, h1);
                *reinterpret_cast<uint32_t*>(&sAlo[row * LDK2 + c0]) = pack2(l0, l1);
            }
        }
    }
    cp_commit_wait();
    __syncthreads();

    #pragma unroll
    for (int i = 0; i < 2; i++)
        #pragma unroll
        for (int j = 0; j < 4; j++)
            #pragma unroll
            for (int e = 0; e < 4; e++) acc[i][j][e] = 0.0f;

    // ---- phase 2: out = ls( h @ W2^T ) ----
    mma_block<8>(
        uAhi + (uint32_t)(arow * LDK2 + acol) * 2,
        uAlo + (uint32_t)(arow * LDK2 + acol) * 2,
        uWhi + (uint32_t)(brow * LDK2 + bcol) * 2,
        uWlo + (uint32_t)(brow * LDK2 + bcol) * 2,
        (uint32_t)LDK2 * 2, acc);

    #pragma unroll
    for (int mf = 0; mf < 2; mf++) {
        #pragma unroll
        for (int nf = 0; nf < 4; nf++) {
            const int c0 = wn * 32 + nf * 8 + cl;
            #pragma unroll
            for (int half = 0; half < 2; half++) {
                const int rg = row0 + wm * 32 + mf * 16 + rl + half * 8;
                float v0 = log_sigmoid(acc[mf][nf][half * 2 + 0]);
                float v1 = log_sigmoid(acc[mf][nf][half * 2 + 1]);
                *reinterpret_cast<float2*>(Cout + (size_t)rg * 128 + c0) =
                    make_float2(v0, v1);
            }
        }
    }
}

// ---------------- kernel: scan mask rows, build adjacency --------------------
// Fast path: 0.5% density -> P(any nonzero in 16B) ~ 2%; integer-test the
// whole float4 once, branch only on hits. Unroll for memory-level parallelism.
__global__ void __launch_bounds__(256)
build_lists_kernel(const float* __restrict__ mask) {
    const int n   = blockIdx.x;
    const int tid = threadIdx.x;
    const uint4* mrow = reinterpret_cast<const uint4*>(mask + (size_t)n * N_EDGES);

    int local[16];
    int c = 0;
    #pragma unroll 4
    for (int i = tid; i < N_EDGES / 4; i += 256) {
        uint4 v = __ldcs(&mrow[i]);
        if (v.x | v.y | v.z | v.w) {
            int e = i * 4;
            if (v.x) { if (c < 16) local[c] = e + 0; c++; }
            if (v.y) { if (c < 16) local[c] = e + 1; c++; }
            if (v.z) { if (c < 16) local[c] = e + 2; c++; }
            if (v.w) { if (c < 16) local[c] = e + 3; c++; }
        }
    }
    c = min(c, 16);

    __shared__ int s_scan[256];
    s_scan[tid] = c;
    __syncthreads();
    #pragma unroll
    for (int off = 1; off < 256; off <<= 1) {
        int v = (tid >= off) ? s_scan[tid - off] : 0;
        __syncthreads();
        s_scan[tid] += v;
        __syncthreads();
    }
    int offset = s_scan[tid] - c;
    int total  = s_scan[255];

    for (int j = 0; j < c; j++) {
        int e   = local[j];
        int pos = offset + j;
        if (pos < NODE_CAP) g_node_edges[n * NODE_CAP + pos] = e;
        int q = atomicAdd(&g_edge_cnt[e], 1);
        if (q < EDGE_CAP) g_edge_nodes[e * EDGE_CAP + q] = n;
    }
    if (tid == 0) g_node_cnt[n] = min(total, NODE_CAP);
}

// ---------------- kernel: nodesum[n] = sum_{e in list(n)} s[e] ---------------
__global__ void __launch_bounds__(128)
node_sum_kernel() {
    const int n = blockIdx.x;
    const int d = threadIdx.x;
    const int cnt = g_node_cnt[n];
    const int* lst = &g_node_edges[n * NODE_CAP];

    float a0 = 0.f, a1 = 0.f, a2 = 0.f, a3 = 0.f;
    int i = 0;
    for (; i + 4 <= cnt; i += 4) {
        int e0 = lst[i], e1 = lst[i + 1], e2 = lst[i + 2], e3 = lst[i + 3];
        a0 += g_s[(size_t)e0 * 128 + d];
        a1 += g_s[(size_t)e1 * 128 + d];
        a2 += g_s[(size_t)e2 * 128 + d];
        a3 += g_s[(size_t)e3 * 128 + d];
    }
    for (; i < cnt; i++) a0 += g_s[(size_t)lst[i] * 128 + d];
    g_nodesum[n * 128 + d] = (a0 + a1) + (a2 + a3);
}

// ---------------- kernel: agg + concat, written pre-split bf16 ---------------
__global__ void __launch_bounds__(128)
edge_gather_kernel(const float* __restrict__ feature) {
    const int e   = blockIdx.x;
    const int tid = threadIdx.x;

    __shared__ int sl[EDGE_CAP];
    __shared__ int ss[EDGE_CAP];
    const int cnt = min(g_edge_cnt[e], EDGE_CAP);

    if (tid < cnt) sl[tid] = g_edge_nodes[e * EDGE_CAP + tid];
    __syncthreads();
    if (tid < cnt) {
        int v = sl[tid];
        int r = 0;
        for (int j = 0; j < cnt; j++) r += (sl[j] < v);
        ss[r] = v;   // node ids unique per edge -> ranks distinct
    }
    __syncthreads();

    float acc = -g_s[(size_t)e * 128 + tid];
    for (int i = 0; i < cnt; i++)
        acc += g_nodesum[ss[i] * 128 + tid];
    {
        __nv_bfloat16 h = __float2bfloat16(acc);
        g_agg_hi[(size_t)e * D_CAT + tid] = h;
        g_agg_lo[(size_t)e * D_CAT + tid] = __float2bfloat16(acc - __bfloat162float(h));
    }
    if (tid < D_FEAT) {
        float f = feature[(size_t)e * D_FEAT + tid];
        __nv_bfloat16 h = __float2bfloat16(f);
        g_agg_hi[(size_t)e * D_CAT + 128 + tid] = h;
        g_agg_lo[(size_t)e * D_CAT + 128 + tid] = __float2bfloat16(f - __bfloat162float(h));
    }
}

// ---------------- launch -----------------------------------------------------
extern "C" void kernel_launch(void* const* d_in, const int* in_sizes, int n_in,
                              void* d_out, int out_size) {
    const float* state   = (const float*)d_in[0];
    const float* feature = (const float*)d_in[1];
    const float* mask    = (const float*)d_in[2];
    // d_in[3] = mask_transpose (unused: exactly mask.T)
    const float* W1_m    = (const float*)d_in[4];
    const float* b1_m    = (const float*)d_in[5];
    const float* W2_m    = (const float*)d_in[6];
    const float* W1_a    = (const float*)d_in[7];
    const float* b1_a    = (const float*)d_in[8];
    const float* W2_a    = (const float*)d_in[9];
    float* out = (float*)d_out;

    // smem: 512 + 2*A(64*LDK1*2) + 2*W(128*LDK1*2)
    const int SMEM_A = 512 + 2 * (64 * 136 * 2) + 2 * (128 * 136 * 2);  // 104,960
    const int SMEM_B = 512 + 2 * (64 * 168 * 2) + 2 * (128 * 168 * 2);  // 129,536
    cudaFuncSetAttribute((const void*)fused_mlp_kernel<128, true>,
                         cudaFuncAttributeMaxDynamicSharedMemorySize, SMEM_A);
    cudaFuncSetAttribute((const void*)fused_mlp_kernel<160, false>,
                         cudaFuncAttributeMaxDynamicSharedMemorySize, SMEM_B);

    float* d_s = nullptr;
    __nv_bfloat16 *d_agg_hi = nullptr, *d_agg_lo = nullptr;
    __nv_bfloat16 *d_w1mh = nullptr, *d_w1ml = nullptr, *d_w2mh = nullptr, *d_w2ml = nullptr;
    __nv_bfloat16 *d_w1ah = nullptr, *d_w1al = nullptr, *d_w2ah = nullptr, *d_w2al = nullptr;
    cudaGetSymbolAddress((void**)&d_s, g_s);
    cudaGetSymbolAddress((void**)&d_agg_hi, g_agg_hi);
    cudaGetSymbolAddress((void**)&d_agg_lo, g_agg_lo);
    cudaGetSymbolAddress((void**)&d_w1mh, g_w1m_hi);
    cudaGetSymbolAddress((void**)&d_w1ml, g_w1m_lo);
    cudaGetSymbolAddress((void**)&d_w2mh, g_w2m_hi);
    cudaGetSymbolAddress((void**)&d_w2ml, g_w2m_lo);
    cudaGetSymbolAddress((void**)&d_w1ah, g_w1a_hi);
    cudaGetSymbolAddress((void**)&d_w1al, g_w1a_lo);
    cudaGetSymbolAddress((void**)&d_w2ah, g_w2a_hi);
    cudaGetSymbolAddress((void**)&d_w2al, g_w2a_lo);

    const int GB = N_EDGES / 64;   // 512 CTAs per fused MLP

    // Fork a side branch for the mask scan so it overlaps the memory MLP.
    // Host objects leak (kernel_launch runs only for correctness + capture;
    // graph replays never re-enter host code).
    cudaStream_t s2;
    cudaStreamCreateWithFlags(&s2, cudaStreamNonBlocking);
    cudaEvent_t evFork, evJoin;
    cudaEventCreateWithFlags(&evFork, cudaEventDisableTiming);
    cudaEventCreateWithFlags(&evJoin, cudaEventDisableTiming);

    // --- fork: branch A (mask scan) on s2 ---
    cudaEventRecord(evFork, 0);
    cudaStreamWaitEvent(s2, evFork, 0);
    zero_edge_cnt_kernel<<<N_EDGES / 256, 256, 0, s2>>>();
    build_lists_kernel<<<N_NODES, 256, 0, s2>>>(mask);
    cudaEventRecord(evJoin, s2);

    // --- branch B (memory MLP) on the main stream, concurrent with A ---
    prep_weights_kernel<<<(128 * 160 + 255) / 256, 256>>>(W1_m, W2_m, W1_a, W2_a);
    fused_mlp_kernel<128, true><<<GB, 256, SMEM_A>>>(
        state, nullptr, nullptr, d_w1mh, d_w1ml, b1_m, d_w2mh, d_w2ml, d_s);

    // --- join: aggregation needs both lists (A) and s (B) ---
    cudaStreamWaitEvent(0, evJoin, 0);
    node_sum_kernel<<<N_NODES, 128>>>();
    edge_gather_kernel<<<N_EDGES, 128>>>(feature);

    // aggregation MLP (fused 2 layers): out = ls(ls(agg@W1a^T+b1a)@W2a^T)
    fused_mlp_kernel<160, false><<<GB, 256, SMEM_B>>>(
        nullptr, d_agg_hi, d_agg_lo, d_w1ah, d_w1al, b1_a, d_w2ah, d_w2al, out);
}